// round 5
// baseline (speedup 1.0000x reference)
#include <cuda_runtime.h>

#define NB    32768
#define N_RX  8

// SYMS = {-3,-1,1,3}/sqrt(5)
#define S_M3 (-1.3416407864998738f)
#define S_M1 (-0.44721359549995793f)
#define S_P1 ( 0.44721359549995793f)
#define S_P3 ( 1.3416407864998738f)
#define LOG2E 1.4426950408889634f
#define LN2   0.6931471805599453f

// select one of 4 register values by 2-bit index (no local memory)
__device__ __forceinline__ float qsel(float a, float b, float c, float d, int i) {
    float ab = (i & 1) ? b : a;
    float cd = (i & 1) ? d : c;
    return (i & 2) ? cd : ab;
}
__device__ __forceinline__ float rowmax4(const float* v) {
    return fmaxf(fmaxf(v[0], v[1]), fmaxf(v[2], v[3]));
}
// Guaranteed single-MUFU ops regardless of fast-math flags
__device__ __forceinline__ float ex2a(float x) {
    float y; asm("ex2.approx.ftz.f32 %0, %1;" : "=f"(y) : "f"(x)); return y;
}
__device__ __forceinline__ float lg2a(float x) {
    float y; asm("lg2.approx.ftz.f32 %0, %1;" : "=f"(y) : "f"(x)); return y;
}
__device__ __forceinline__ float rcpa(float x) {
    float y; asm("rcp.approx.ftz.f32 %0, %1;" : "=f"(y) : "f"(x)); return y;
}

__global__ __launch_bounds__(256, 3)
void mfnet_layer_kernel(const float* __restrict__ log_qi_in,
                        const float* __restrict__ G,
                        const float* __restrict__ sqrt_2rho,
                        const float* __restrict__ alpha_ptr,
                        float* __restrict__ out)
{
    const int gtid = blockIdx.x * blockDim.x + threadIdx.x;
    const int b    = gtid >> 5;          // one warp per batch item
    const int lane = gtid & 31;
    if (b >= NB) return;

    const float alpha = __ldg(alpha_ptr);
    const float rho2  = __ldg(&sqrt_2rho[b]) * LOG2E;   // log2 units
    const float rho2n = -rho2;

    // k = i0*64 + i1*16 + i2*4 + i3 ; k = lane*8 + j
    // i0 = lane>>3, i1 = (lane>>1)&3, i2 = 2*lb + (j>>2), i3 = j&3
    const int i0 = lane >> 3;
    const int i1 = (lane >> 1) & 3;
    const int lb = lane & 1;
    const int bit1 = (lane >> 1) & 1;
    const int bit0 = lane & 1;

    const float s0 = qsel(S_M3, S_M1, S_P1, S_P3, i0);
    const float s1 = qsel(S_M3, S_M1, S_P1, S_P3, i1);
    const float rs0    = rho2n * s0;
    const float rs1    = rho2n * s1;
    const float rsi2_0 = rho2n * (lb ? S_P1 : S_M3);
    const float rsi2_1 = rho2n * (lb ? S_P3 : S_M1);
    const float rp1    = rho2n * S_P1;

    // ---- Laplace: lp2[j] = Sum_r x2 + log2( Prod_r e*(1-0.5e) ), e = min(2^{xn},1) ----
    // xn = -x2 = t2n[r][jc] + c3n[r]*si3 ; 2^{xn} = A_jc * C_i3 (exp factorization)
    float prod[8] = {1.f,1.f,1.f,1.f,1.f,1.f,1.f,1.f};
    float st0 = 0.f, st1 = 0.f, sgw = 0.f;
    const float4* Gv = reinterpret_cast<const float4*>(G) + (size_t)b * N_RX;
    #pragma unroll
    for (int r = 0; r < N_RX; r++) {
        float4 g = Gv[r];
        float basen = fmaf(g.x, rs0, g.y * rs1);
        float t0 = fmaf(g.z, rsi2_0, basen);
        float t1 = fmaf(g.z, rsi2_1, basen);
        st0 += t0; st1 += t1; sgw += g.w;
        float cb  = g.w * rp1;
        float A0  = ex2a(t0);
        float A1  = ex2a(t1);
        float B   = ex2a(cb);
        float iB  = rcpa(B);
        float B3  = (B * B) * B;
        float iB3 = (iB * iB) * iB;
        float C[4] = {iB3, iB, B, B3};   // i3 = 0..3 -> {-3,-1,+1,+3}*u
        #pragma unroll
        for (int j = 0; j < 8; j++) {
            float A = (j >> 2) ? A1 : A0;
            float v = A * C[j & 3];
            float e = fminf(v, 1.0f);
            float h = fmaf(-0.5f, e, 1.0f);
            prod[j] *= e * h;
        }
    }
    const float Tp0 = -st0, Tp1 = -st1;
    const float Cp  = rho2 * sgw;        // = -rho2n * sgw
    const float SY[4] = {S_M3, S_M1, S_P1, S_P3};
    float lp2[8];
    #pragma unroll
    for (int j = 0; j < 8; j++) {
        float sx = fmaf(Cp, SY[j & 3], (j >> 2) ? Tp1 : Tp0);
        lp2[j] = sx + lg2a(fmaxf(prod[j], 1e-37f));
    }

    // ---- Load log_qi, convert to log2 units; lazy per-row offsets ----
    float lq[4][4], off[4];
    const float4* Lv = reinterpret_cast<const float4*>(log_qi_in) + (size_t)b * 4;
    #pragma unroll
    for (int t = 0; t < 4; t++) {
        float4 v = Lv[t];
        lq[t][0] = v.x * LOG2E; lq[t][1] = v.y * LOG2E;
        lq[t][2] = v.z * LOG2E; lq[t][3] = v.w * LOG2E;
    }
    off[0] = 0.0f;               // row 0's first update uses the raw row
    off[1] = rowmax4(lq[1]);
    off[2] = rowmax4(lq[2]);
    off[3] = rowmax4(lq[3]);

    // ---- Initial unnormalized softmax pieces (normalization deferred to per-xi scale) ----
    float f1, e2s0, e2s1, S0, S1, S2, S3;
    float f0;
    {
        float e0 = ex2a(lq[0][0]), e1 = ex2a(lq[0][1]), e2 = ex2a(lq[0][2]), e3 = ex2a(lq[0][3]);
        S0 = (e0 + e1) + (e2 + e3);
        f0 = qsel(e0, e1, e2, e3, i0);
    }
    {
        float e0 = ex2a(lq[1][0]-off[1]), e1 = ex2a(lq[1][1]-off[1]);
        float e2 = ex2a(lq[1][2]-off[1]), e3 = ex2a(lq[1][3]-off[1]);
        S1 = (e0 + e1) + (e2 + e3);
        f1 = qsel(e0, e1, e2, e3, i1);
    }
    {
        float e0 = ex2a(lq[2][0]-off[2]), e1 = ex2a(lq[2][1]-off[2]);
        float e2 = ex2a(lq[2][2]-off[2]), e3 = ex2a(lq[2][3]-off[2]);
        S2 = (e0 + e1) + (e2 + e3);
        e2s0 = lb ? e2 : e0;
        e2s1 = lb ? e3 : e1;
    }
    float ul0, ul1;
    {
        float e0 = ex2a(lq[3][0]-off[3]), e1 = ex2a(lq[3][1]-off[3]);
        float e2 = ex2a(lq[3][2]-off[3]), e3 = ex2a(lq[3][3]-off[3]);
        S3 = (e0 + e1) + (e2 + e3);
        ul0 = fmaf(e3, lp2[3], fmaf(e2, lp2[2], fmaf(e1, lp2[1], e0 * lp2[0])));
        ul1 = fmaf(e3, lp2[7], fmaf(e2, lp2[6], fmaf(e1, lp2[5], e0 * lp2[4])));
    }
    float sum_wl = fmaf(e2s1, ul1, e2s0 * ul0);
    const float S23 = S2 * S3;
    const float oma = 1.0f - alpha;
    const unsigned FULL = 0xffffffffu;

    float S0n, S1n, f01;

    // ---- xi = 0 : bucket i0 (bits 3,4); reduce bits 0,1,2; scale 1/(S1*S2*S3) ----
    {
        float a = f1 * sum_wl;
        a += __shfl_xor_sync(FULL, a, 1);
        a += __shfl_xor_sync(FULL, a, 2);
        a += __shfl_xor_sync(FULL, a, 4);
        float a0 = __shfl_sync(FULL, a, 0);
        float a1 = __shfl_sync(FULL, a, 8);
        float a2 = __shfl_sync(FULL, a, 16);
        float a3 = __shfl_sync(FULL, a, 24);
        float sc = alpha * rcpa(S1 * S23);
        lq[0][0] = fmaf(oma, lq[0][0], sc * a0);
        lq[0][1] = fmaf(oma, lq[0][1], sc * a1);
        lq[0][2] = fmaf(oma, lq[0][2], sc * a2);
        lq[0][3] = fmaf(oma, lq[0][3], sc * a3);
        off[0] = rowmax4(lq[0]);
        float e0 = ex2a(lq[0][0]-off[0]), e1 = ex2a(lq[0][1]-off[0]);
        float e2 = ex2a(lq[0][2]-off[0]), e3 = ex2a(lq[0][3]-off[0]);
        S0n = (e0 + e1) + (e2 + e3);
        f0 = qsel(e0, e1, e2, e3, i0);
    }

    // ---- xi = 1 : bucket i1 (bits 1,2); reduce bits 0,3,4; scale 1/(S0n*S2*S3) ----
    {
        float a = f0 * sum_wl;
        a += __shfl_xor_sync(FULL, a, 1);
        a += __shfl_xor_sync(FULL, a, 8);
        a += __shfl_xor_sync(FULL, a, 16);
        float a0 = __shfl_sync(FULL, a, 0);
        float a1 = __shfl_sync(FULL, a, 2);
        float a2 = __shfl_sync(FULL, a, 4);
        float a3 = __shfl_sync(FULL, a, 6);
        float sc = alpha * rcpa(S0n * S23);
        float o = off[1];
        lq[1][0] = fmaf(oma, lq[1][0] - o, sc * a0);
        lq[1][1] = fmaf(oma, lq[1][1] - o, sc * a1);
        lq[1][2] = fmaf(oma, lq[1][2] - o, sc * a2);
        lq[1][3] = fmaf(oma, lq[1][3] - o, sc * a3);
        off[1] = rowmax4(lq[1]);
        float e0 = ex2a(lq[1][0]-off[1]), e1 = ex2a(lq[1][1]-off[1]);
        float e2 = ex2a(lq[1][2]-off[1]), e3 = ex2a(lq[1][3]-off[1]);
        S1n = (e0 + e1) + (e2 + e3);
        float f1n = qsel(e0, e1, e2, e3, i1);
        f01 = f0 * f1n;
    }

    // ---- xi = 2 : bucket 2*lb + jc; fold xor2, reduce 4,8,16; scale 1/(S0n*S1n*S3) ----
    float g0, g1, S01;
    {
        float a0 = f01 * ul0;   // bucket 2*lb
        float a1 = f01 * ul1;   // bucket 2*lb+1
        // fold: lane owns bucket 2*lb + bit1
        float keep = bit1 ? a1 : a0;
        float send = bit1 ? a0 : a1;
        float a = keep + __shfl_xor_sync(FULL, send, 2);
        a += __shfl_xor_sync(FULL, a, 4);
        a += __shfl_xor_sync(FULL, a, 8);
        a += __shfl_xor_sync(FULL, a, 16);
        float b0 = __shfl_sync(FULL, a, 0);   // lb=0,bit1=0
        float b1 = __shfl_sync(FULL, a, 2);   // lb=0,bit1=1
        float b2 = __shfl_sync(FULL, a, 1);   // lb=1,bit1=0
        float b3 = __shfl_sync(FULL, a, 3);   // lb=1,bit1=1
        S01 = S0n * S1n;
        float sc = alpha * rcpa(S01 * S3);
        float o = off[2];
        lq[2][0] = fmaf(oma, lq[2][0] - o, sc * b0);
        lq[2][1] = fmaf(oma, lq[2][1] - o, sc * b1);
        lq[2][2] = fmaf(oma, lq[2][2] - o, sc * b2);
        lq[2][3] = fmaf(oma, lq[2][3] - o, sc * b3);
        off[2] = rowmax4(lq[2]);
        float e0 = ex2a(lq[2][0]-off[2]), e1 = ex2a(lq[2][1]-off[2]);
        float e2 = ex2a(lq[2][2]-off[2]), e3 = ex2a(lq[2][3]-off[2]);
        float S2n = (e0 + e1) + (e2 + e3);
        g0 = f01 * (lb ? e2 : e0);
        g1 = f01 * (lb ? e3 : e1);
        S23 /* dead */;
        // stash S2n into S3 slot for xi=3 scale
        S3 = S2n;
    }

    // ---- xi = 3 : bucket i3; fold 4->1 (xor1 x2, xor2), reduce 4,8,16; scale 1/(S0n*S1n*S2n) ----
    {
        float v0 = fmaf(g1, lp2[4], g0 * lp2[0]);
        float v1 = fmaf(g1, lp2[5], g0 * lp2[1]);
        float v2 = fmaf(g1, lp2[6], g0 * lp2[2]);
        float v3 = fmaf(g1, lp2[7], g0 * lp2[3]);
        // fold buckets into lane bits: keep b0==bit0
        float kA = bit0 ? v1 : v0, sA = bit0 ? v0 : v1;
        float kB = bit0 ? v3 : v2, sB = bit0 ? v2 : v3;
        float rA = kA + __shfl_xor_sync(FULL, sA, 1);  // bucket bit0
        float rB = kB + __shfl_xor_sync(FULL, sB, 1);  // bucket 2+bit0
        float k2 = bit1 ? rB : rA, s2 = bit1 ? rA : rB;
        float a = k2 + __shfl_xor_sync(FULL, s2, 2);   // bucket lane&3
        a += __shfl_xor_sync(FULL, a, 4);
        a += __shfl_xor_sync(FULL, a, 8);
        a += __shfl_xor_sync(FULL, a, 16);
        float b0 = __shfl_sync(FULL, a, 0);
        float b1 = __shfl_sync(FULL, a, 1);
        float b2 = __shfl_sync(FULL, a, 2);
        float b3 = __shfl_sync(FULL, a, 3);
        float sc = alpha * rcpa(S01 * S3);   // S3 holds S2n
        float o = off[3];
        lq[3][0] = fmaf(oma, lq[3][0] - o, sc * b0);
        lq[3][1] = fmaf(oma, lq[3][1] - o, sc * b1);
        lq[3][2] = fmaf(oma, lq[3][2] - o, sc * b2);
        lq[3][3] = fmaf(oma, lq[3][3] - o, sc * b3);
        off[3] = rowmax4(lq[3]);
    }

    // ---- Output: (stored - off) * ln2, lanes 0..3 write rows 0..3 ----
    float o0 = off[0], o1 = off[1], o2 = off[2], o3 = off[3];
    float r0 = qsel(lq[0][0]-o0, lq[1][0]-o1, lq[2][0]-o2, lq[3][0]-o3, lane) * LN2;
    float r1 = qsel(lq[0][1]-o0, lq[1][1]-o1, lq[2][1]-o2, lq[3][1]-o3, lane) * LN2;
    float r2 = qsel(lq[0][2]-o0, lq[1][2]-o1, lq[2][2]-o2, lq[3][2]-o3, lane) * LN2;
    float r3 = qsel(lq[0][3]-o0, lq[1][3]-o1, lq[2][3]-o2, lq[3][3]-o3, lane) * LN2;
    if (lane < 4) {
        reinterpret_cast<float4*>(out)[(size_t)b * 4 + lane] = make_float4(r0, r1, r2, r3);
    }
}

extern "C" void kernel_launch(void* const* d_in, const int* in_sizes, int n_in,
                              void* d_out, int out_size)
{
    const float* log_qi    = (const float*)d_in[0]; // (N,4,4)
    const float* G         = (const float*)d_in[1]; // (N,8,4)
    const float* sqrt_2rho = (const float*)d_in[2]; // (N,)
    // d_in[3] = n_var, unused by reference
    const float* alpha     = (const float*)d_in[4]; // scalar

    float* out = (float*)d_out;

    const int threads = 256;                 // 8 warps/block
    const int blocks  = (NB * 32) / threads; // 4096
    mfnet_layer_kernel<<<blocks, threads>>>(log_qi, G, sqrt_2rho, alpha, out);
}

// round 6
// speedup vs baseline: 1.1061x; 1.1061x over previous
#include <cuda_runtime.h>

#define NB    32768
#define N_RX  8

// SYMS = {-3,-1,1,3}/sqrt(5)
#define S_M3 (-1.3416407864998738f)
#define S_M1 (-0.44721359549995793f)
#define S_P1 ( 0.44721359549995793f)
#define S_P3 ( 1.3416407864998738f)
#define LOG2E 1.4426950408889634f
#define LN2   0.6931471805599453f

typedef unsigned long long u64;

// select one of 4 register values by 2-bit index (no local memory)
__device__ __forceinline__ float qsel(float a, float b, float c, float d, int i) {
    float ab = (i & 1) ? b : a;
    float cd = (i & 1) ? d : c;
    return (i & 2) ? cd : ab;
}
__device__ __forceinline__ float rowmax4(const float* v) {
    return fmaxf(fmaxf(v[0], v[1]), fmaxf(v[2], v[3]));
}
// Guaranteed single-MUFU ops regardless of fast-math flags
__device__ __forceinline__ float ex2a(float x) {
    float y; asm("ex2.approx.ftz.f32 %0, %1;" : "=f"(y) : "f"(x)); return y;
}
__device__ __forceinline__ float lg2a(float x) {
    float y; asm("lg2.approx.ftz.f32 %0, %1;" : "=f"(y) : "f"(x)); return y;
}
__device__ __forceinline__ float rcpa(float x) {
    float y; asm("rcp.approx.ftz.f32 %0, %1;" : "=f"(y) : "f"(x)); return y;
}
// Packed f32x2 helpers (FFMA2/FMUL2 paths on sm_103a)
__device__ __forceinline__ u64 pk2(float lo, float hi) {
    u64 d; asm("mov.b64 %0, {%1, %2};" : "=l"(d) : "f"(lo), "f"(hi)); return d;
}
__device__ __forceinline__ void upk2(float& lo, float& hi, u64 d) {
    asm("mov.b64 {%0, %1}, %2;" : "=f"(lo), "=f"(hi) : "l"(d));
}
__device__ __forceinline__ u64 mul2(u64 a, u64 b) {
    u64 d; asm("mul.rn.f32x2 %0, %1, %2;" : "=l"(d) : "l"(a), "l"(b)); return d;
}
__device__ __forceinline__ u64 fma2(u64 a, u64 b, u64 c) {
    u64 d; asm("fma.rn.f32x2 %0, %1, %2, %3;" : "=l"(d) : "l"(a), "l"(b), "l"(c)); return d;
}

__global__ __launch_bounds__(128, 7)
void mfnet_layer_kernel(const float* __restrict__ log_qi_in,
                        const float* __restrict__ G,
                        const float* __restrict__ sqrt_2rho,
                        const float* __restrict__ alpha_ptr,
                        float* __restrict__ out)
{
    const int gtid = blockIdx.x * blockDim.x + threadIdx.x;
    const int b    = gtid >> 5;          // one warp per batch item
    const int lane = gtid & 31;
    if (b >= NB) return;

    const float alpha = __ldg(alpha_ptr);
    const float rho2  = __ldg(&sqrt_2rho[b]) * LOG2E;   // log2 units
    const float rho2n = -rho2;

    // k = i0*64 + i1*16 + i2*4 + i3 ; k = lane*8 + j
    // i0 = lane>>3, i1 = (lane>>1)&3, i2 = 2*lb + (j>>2), i3 = j&3
    const int i0 = lane >> 3;
    const int i1 = (lane >> 1) & 3;
    const int lb = lane & 1;
    const int bit1 = (lane >> 1) & 1;
    const int bit0 = lane & 1;

    const float s0 = qsel(S_M3, S_M1, S_P1, S_P3, i0);
    const float s1 = qsel(S_M3, S_M1, S_P1, S_P3, i1);
    const float rs0    = rho2n * s0;
    const float rs1    = rho2n * s1;
    const float rsi2_0 = rho2n * (lb ? S_P1 : S_M3);
    const float rsi2_1 = rho2n * (lb ? S_P3 : S_M1);
    const float rp1    = rho2n * S_P1;

    // ---- Laplace (log2 units), exp-factorized + f32x2-packed ----
    // xn = -x = t_jc + cb*m(i3), m in {-3,-1,1,3};  2^{xn} = A_jc * C_i3
    // e = min(2^{xn}, 1);  m = e*(1 - 0.5e);  lp2[j] = Sum x + log2(Prod m)
    // prod pairs: p = jc*2 + (i3>>1); lo half = even i3, hi half = odd i3.
    const u64 NH2  = pk2(-0.5f, -0.5f);
    const u64 ONE2 = pk2(1.0f, 1.0f);
    u64 prod2[4] = {ONE2, ONE2, ONE2, ONE2};
    float st0 = 0.f, st1 = 0.f, sgw = 0.f;
    const float4* Gv = reinterpret_cast<const float4*>(G) + (size_t)b * N_RX;
    #pragma unroll
    for (int r = 0; r < N_RX; r++) {
        float4 g = Gv[r];
        float basen = fmaf(g.x, rs0, g.y * rs1);
        float t0 = fmaf(g.z, rsi2_0, basen);
        float t1 = fmaf(g.z, rsi2_1, basen);
        st0 += t0; st1 += t1; sgw += g.w;
        float cb  = g.w * rp1;
        float A0  = ex2a(t0);
        float A1  = ex2a(t1);
        float B   = ex2a(cb);
        float iB  = rcpa(B);
        float B3  = (B * B) * B;
        float iB3 = (iB * iB) * iB;
        u64 A2[2] = { pk2(A0, A0), pk2(A1, A1) };
        u64 C2[2] = { pk2(iB3, iB), pk2(B, B3) };
        #pragma unroll
        for (int p = 0; p < 4; p++) {
            u64 v2 = mul2(A2[p >> 1], C2[p & 1]);
            float vlo, vhi;
            upk2(vlo, vhi, v2);
            float elo = fminf(vlo, 1.0f);
            float ehi = fminf(vhi, 1.0f);
            u64 e2 = pk2(elo, ehi);
            u64 h2 = fma2(NH2, e2, ONE2);
            u64 m2 = mul2(e2, h2);
            prod2[p] = mul2(prod2[p], m2);
        }
    }
    const float Tp0 = -st0, Tp1 = -st1;
    const float Cp  = rho2 * sgw;
    const float SY[4] = {S_M3, S_M1, S_P1, S_P3};
    float lp2[8];
    #pragma unroll
    for (int p = 0; p < 4; p++) {
        float plo, phi;
        upk2(plo, phi, prod2[p]);
        const int jc  = p >> 1;
        const int i3a = (p & 1) * 2;          // even i3 in lo half
        const float Tp = jc ? Tp1 : Tp0;
        lp2[jc * 4 + i3a]     = fmaf(Cp, SY[i3a],     Tp) + lg2a(fmaxf(plo, 1e-37f));
        lp2[jc * 4 + i3a + 1] = fmaf(Cp, SY[i3a + 1], Tp) + lg2a(fmaxf(phi, 1e-37f));
    }

    // ---- Load log_qi, convert to log2 units; lazy per-row offsets ----
    float lq[4][4], off[4];
    const float4* Lv = reinterpret_cast<const float4*>(log_qi_in) + (size_t)b * 4;
    #pragma unroll
    for (int t = 0; t < 4; t++) {
        float4 v = Lv[t];
        lq[t][0] = v.x * LOG2E; lq[t][1] = v.y * LOG2E;
        lq[t][2] = v.z * LOG2E; lq[t][3] = v.w * LOG2E;
    }
    off[0] = 0.0f;               // row 0's first update uses the raw row
    off[1] = rowmax4(lq[1]);
    off[2] = rowmax4(lq[2]);
    off[3] = rowmax4(lq[3]);

    // ---- Initial unnormalized softmax pieces (normalization deferred to per-xi scale) ----
    float f0, f1, e2s0, e2s1, S1, S2, S3;
    {
        float e0 = ex2a(lq[0][0]), e1 = ex2a(lq[0][1]), e2 = ex2a(lq[0][2]), e3 = ex2a(lq[0][3]);
        f0 = qsel(e0, e1, e2, e3, i0);
    }
    {
        float e0 = ex2a(lq[1][0]-off[1]), e1 = ex2a(lq[1][1]-off[1]);
        float e2 = ex2a(lq[1][2]-off[1]), e3 = ex2a(lq[1][3]-off[1]);
        S1 = (e0 + e1) + (e2 + e3);
        f1 = qsel(e0, e1, e2, e3, i1);
    }
    {
        float e0 = ex2a(lq[2][0]-off[2]), e1 = ex2a(lq[2][1]-off[2]);
        float e2 = ex2a(lq[2][2]-off[2]), e3 = ex2a(lq[2][3]-off[2]);
        S2 = (e0 + e1) + (e2 + e3);
        e2s0 = lb ? e2 : e0;
        e2s1 = lb ? e3 : e1;
    }
    float ul0, ul1;
    {
        float e0 = ex2a(lq[3][0]-off[3]), e1 = ex2a(lq[3][1]-off[3]);
        float e2 = ex2a(lq[3][2]-off[3]), e3 = ex2a(lq[3][3]-off[3]);
        S3 = (e0 + e1) + (e2 + e3);
        ul0 = fmaf(e3, lp2[3], fmaf(e2, lp2[2], fmaf(e1, lp2[1], e0 * lp2[0])));
        ul1 = fmaf(e3, lp2[7], fmaf(e2, lp2[6], fmaf(e1, lp2[5], e0 * lp2[4])));
    }
    float sum_wl = fmaf(e2s1, ul1, e2s0 * ul0);
    float S23 = S2 * S3;
    const float oma = 1.0f - alpha;
    const unsigned FULL = 0xffffffffu;

    float S0n, S1n, f01;

    // ---- xi = 0 : bucket i0 (bits 3,4); reduce bits 0,1,2; scale 1/(S1*S2*S3) ----
    {
        float a = f1 * sum_wl;
        a += __shfl_xor_sync(FULL, a, 1);
        a += __shfl_xor_sync(FULL, a, 2);
        a += __shfl_xor_sync(FULL, a, 4);
        float a0 = __shfl_sync(FULL, a, 0);
        float a1 = __shfl_sync(FULL, a, 8);
        float a2 = __shfl_sync(FULL, a, 16);
        float a3 = __shfl_sync(FULL, a, 24);
        float sc = alpha * rcpa(S1 * S23);
        lq[0][0] = fmaf(oma, lq[0][0], sc * a0);
        lq[0][1] = fmaf(oma, lq[0][1], sc * a1);
        lq[0][2] = fmaf(oma, lq[0][2], sc * a2);
        lq[0][3] = fmaf(oma, lq[0][3], sc * a3);
        off[0] = rowmax4(lq[0]);
        float e0 = ex2a(lq[0][0]-off[0]), e1 = ex2a(lq[0][1]-off[0]);
        float e2 = ex2a(lq[0][2]-off[0]), e3 = ex2a(lq[0][3]-off[0]);
        S0n = (e0 + e1) + (e2 + e3);
        f0 = qsel(e0, e1, e2, e3, i0);
    }

    // ---- xi = 1 : bucket i1 (bits 1,2); reduce bits 0,3,4; scale 1/(S0n*S2*S3) ----
    {
        float a = f0 * sum_wl;
        a += __shfl_xor_sync(FULL, a, 1);
        a += __shfl_xor_sync(FULL, a, 8);
        a += __shfl_xor_sync(FULL, a, 16);
        float a0 = __shfl_sync(FULL, a, 0);
        float a1 = __shfl_sync(FULL, a, 2);
        float a2 = __shfl_sync(FULL, a, 4);
        float a3 = __shfl_sync(FULL, a, 6);
        float sc = alpha * rcpa(S0n * S23);
        float o = off[1];
        lq[1][0] = fmaf(oma, lq[1][0] - o, sc * a0);
        lq[1][1] = fmaf(oma, lq[1][1] - o, sc * a1);
        lq[1][2] = fmaf(oma, lq[1][2] - o, sc * a2);
        lq[1][3] = fmaf(oma, lq[1][3] - o, sc * a3);
        off[1] = rowmax4(lq[1]);
        float e0 = ex2a(lq[1][0]-off[1]), e1 = ex2a(lq[1][1]-off[1]);
        float e2 = ex2a(lq[1][2]-off[1]), e3 = ex2a(lq[1][3]-off[1]);
        S1n = (e0 + e1) + (e2 + e3);
        float f1n = qsel(e0, e1, e2, e3, i1);
        f01 = f0 * f1n;
    }

    // ---- xi = 2 : bucket 2*lb + jc; fold xor2, reduce 4,8,16; scale 1/(S0n*S1n*S3) ----
    float g0, g1, S01;
    {
        float a0 = f01 * ul0;   // bucket 2*lb
        float a1 = f01 * ul1;   // bucket 2*lb+1
        // fold: lane owns bucket 2*lb + bit1
        float keep = bit1 ? a1 : a0;
        float send = bit1 ? a0 : a1;
        float a = keep + __shfl_xor_sync(FULL, send, 2);
        a += __shfl_xor_sync(FULL, a, 4);
        a += __shfl_xor_sync(FULL, a, 8);
        a += __shfl_xor_sync(FULL, a, 16);
        float b0 = __shfl_sync(FULL, a, 0);   // lb=0,bit1=0
        float b1 = __shfl_sync(FULL, a, 2);   // lb=0,bit1=1
        float b2 = __shfl_sync(FULL, a, 1);   // lb=1,bit1=0
        float b3 = __shfl_sync(FULL, a, 3);   // lb=1,bit1=1
        S01 = S0n * S1n;
        float sc = alpha * rcpa(S01 * S3);
        float o = off[2];
        lq[2][0] = fmaf(oma, lq[2][0] - o, sc * b0);
        lq[2][1] = fmaf(oma, lq[2][1] - o, sc * b1);
        lq[2][2] = fmaf(oma, lq[2][2] - o, sc * b2);
        lq[2][3] = fmaf(oma, lq[2][3] - o, sc * b3);
        off[2] = rowmax4(lq[2]);
        float e0 = ex2a(lq[2][0]-off[2]), e1 = ex2a(lq[2][1]-off[2]);
        float e2 = ex2a(lq[2][2]-off[2]), e3 = ex2a(lq[2][3]-off[2]);
        float S2n = (e0 + e1) + (e2 + e3);
        g0 = f01 * (lb ? e2 : e0);
        g1 = f01 * (lb ? e3 : e1);
        S3 = S2n;   // reuse slot for xi=3 scale
    }

    // ---- xi = 3 : bucket i3; fold 4->1 (xor1, xor2), reduce 4,8,16; scale 1/(S0n*S1n*S2n) ----
    {
        float v0 = fmaf(g1, lp2[4], g0 * lp2[0]);
        float v1 = fmaf(g1, lp2[5], g0 * lp2[1]);
        float v2 = fmaf(g1, lp2[6], g0 * lp2[2]);
        float v3 = fmaf(g1, lp2[7], g0 * lp2[3]);
        // fold buckets into lane bits: keep b0==bit0
        float kA = bit0 ? v1 : v0, sA = bit0 ? v0 : v1;
        float kB = bit0 ? v3 : v2, sB = bit0 ? v2 : v3;
        float rA = kA + __shfl_xor_sync(FULL, sA, 1);  // bucket bit0
        float rB = kB + __shfl_xor_sync(FULL, sB, 1);  // bucket 2+bit0
        float k2 = bit1 ? rB : rA, s2 = bit1 ? rA : rB;
        float a = k2 + __shfl_xor_sync(FULL, s2, 2);   // bucket lane&3
        a += __shfl_xor_sync(FULL, a, 4);
        a += __shfl_xor_sync(FULL, a, 8);
        a += __shfl_xor_sync(FULL, a, 16);
        float b0 = __shfl_sync(FULL, a, 0);
        float b1 = __shfl_sync(FULL, a, 1);
        float b2 = __shfl_sync(FULL, a, 2);
        float b3 = __shfl_sync(FULL, a, 3);
        float sc = alpha * rcpa(S01 * S3);   // S3 holds S2n
        float o = off[3];
        lq[3][0] = fmaf(oma, lq[3][0] - o, sc * b0);
        lq[3][1] = fmaf(oma, lq[3][1] - o, sc * b1);
        lq[3][2] = fmaf(oma, lq[3][2] - o, sc * b2);
        lq[3][3] = fmaf(oma, lq[3][3] - o, sc * b3);
        off[3] = rowmax4(lq[3]);
    }

    // ---- Output: (stored - off) * ln2, lanes 0..3 write rows 0..3 ----
    float o0 = off[0], o1 = off[1], o2 = off[2], o3 = off[3];
    float r0 = qsel(lq[0][0]-o0, lq[1][0]-o1, lq[2][0]-o2, lq[3][0]-o3, lane) * LN2;
    float r1 = qsel(lq[0][1]-o0, lq[1][1]-o1, lq[2][1]-o2, lq[3][1]-o3, lane) * LN2;
    float r2 = qsel(lq[0][2]-o0, lq[1][2]-o1, lq[2][2]-o2, lq[3][2]-o3, lane) * LN2;
    float r3 = qsel(lq[0][3]-o0, lq[1][3]-o1, lq[2][3]-o2, lq[3][3]-o3, lane) * LN2;
    if (lane < 4) {
        reinterpret_cast<float4*>(out)[(size_t)b * 4 + lane] = make_float4(r0, r1, r2, r3);
    }
}

extern "C" void kernel_launch(void* const* d_in, const int* in_sizes, int n_in,
                              void* d_out, int out_size)
{
    const float* log_qi    = (const float*)d_in[0]; // (N,4,4)
    const float* G         = (const float*)d_in[1]; // (N,8,4)
    const float* sqrt_2rho = (const float*)d_in[2]; // (N,)
    // d_in[3] = n_var, unused by reference
    const float* alpha     = (const float*)d_in[4]; // scalar

    float* out = (float*)d_out;

    const int threads = 128;                 // 4 warps/block, 7 blocks/SM target
    const int blocks  = (NB * 32) / threads; // 8192
    mfnet_layer_kernel<<<blocks, threads>>>(log_qi, G, sqrt_2rho, alpha, out);
}

// round 7
// speedup vs baseline: 1.4105x; 1.2752x over previous
#include <cuda_runtime.h>

#define NB    32768
#define N_RX  8

// SYMS = {-3,-1,1,3}/sqrt(5)
#define S_M3 (-1.3416407864998738f)
#define S_M1 (-0.44721359549995793f)
#define S_P1 ( 0.44721359549995793f)
#define S_P3 ( 1.3416407864998738f)
#define LOG2E 1.4426950408889634f
#define LN2   0.6931471805599453f

typedef unsigned long long u64;

__device__ __forceinline__ float qsel(float a, float b, float c, float d, int i) {
    float ab = (i & 1) ? b : a;
    float cd = (i & 1) ? d : c;
    return (i & 2) ? cd : ab;
}
__device__ __forceinline__ float rowmax4(const float* v) {
    return fmaxf(fmaxf(v[0], v[1]), fmaxf(v[2], v[3]));
}
__device__ __forceinline__ float ex2a(float x) {
    float y; asm("ex2.approx.ftz.f32 %0, %1;" : "=f"(y) : "f"(x)); return y;
}
__device__ __forceinline__ float lg2a(float x) {
    float y; asm("lg2.approx.ftz.f32 %0, %1;" : "=f"(y) : "f"(x)); return y;
}
__device__ __forceinline__ float rcpa(float x) {
    float y; asm("rcp.approx.ftz.f32 %0, %1;" : "=f"(y) : "f"(x)); return y;
}
__device__ __forceinline__ u64 pk2(float lo, float hi) {
    u64 d; asm("mov.b64 %0, {%1, %2};" : "=l"(d) : "f"(lo), "f"(hi)); return d;
}
__device__ __forceinline__ void upk2(float& lo, float& hi, u64 d) {
    asm("mov.b64 {%0, %1}, %2;" : "=f"(lo), "=f"(hi) : "l"(d));
}
__device__ __forceinline__ u64 mul2(u64 a, u64 b) {
    u64 d; asm("mul.rn.f32x2 %0, %1, %2;" : "=l"(d) : "l"(a), "l"(b)); return d;
}
__device__ __forceinline__ u64 fma2(u64 a, u64 b, u64 c) {
    u64 d; asm("fma.rn.f32x2 %0, %1, %2, %3;" : "=l"(d) : "l"(a), "l"(b), "l"(c)); return d;
}

__global__ __launch_bounds__(128, 7)
void mfnet_layer_kernel(const float* __restrict__ log_qi_in,
                        const float* __restrict__ G,
                        const float* __restrict__ sqrt_2rho,
                        const float* __restrict__ alpha_ptr,
                        float* __restrict__ out)
{
    const int gtid = blockIdx.x * blockDim.x + threadIdx.x;
    const int w    = gtid >> 5;
    const int lane = gtid & 31;
    // Two items per warp: half-warps own item b = 2w + half.
    const int half = lane >> 4;
    const int hl   = lane & 15;
    const int b    = 2 * w + half;
    const int base = lane & 16;          // half-warp base lane for broadcasts

    const float alpha = __ldg(alpha_ptr);
    const float rho2  = __ldg(&sqrt_2rho[b]) * LOG2E;   // log2 units
    const float rho2n = -rho2;

    // k = i0*64 + i1*16 + i2*4 + i3 ; k = hl*16 + j
    // i0 = hl>>2, i1 = hl&3, i2 = j>>2, i3 = j&3
    const int i0 = hl >> 2;
    const int i1 = hl & 3;
    const int bit0 = hl & 1;
    const int bit1 = (hl >> 1) & 1;

    const float rs0 = rho2n * qsel(S_M3, S_M1, S_P1, S_P3, i0);
    const float rs1 = rho2n * qsel(S_M3, S_M1, S_P1, S_P3, i1);
    const float rm3 = rho2n * S_M3;
    const float rm1 = rho2n * S_M1;
    const float rp1 = rho2n * S_P1;
    const float rp3 = rho2n * S_P3;

    // ---- Laplace (log2 units), exp-factorized + f32x2-packed, 16 j per lane ----
    // xn = -x = t_{i2} + cb*m(i3), m in {-3,-1,1,3};  2^{xn} = A_{i2} * C_{i3}
    // e = min(2^{xn},1);  mterm = e*(1-0.5e);  lp2[j] = Sum_r x + log2(Prod_r mterm)
    const u64 NH2  = pk2(-0.5f, -0.5f);
    const u64 ONE2 = pk2(1.0f, 1.0f);
    u64 prod2[8] = {ONE2, ONE2, ONE2, ONE2, ONE2, ONE2, ONE2, ONE2};
    float SB = 0.f, SGZ = 0.f, SGW = 0.f;
    const float4* Gv = reinterpret_cast<const float4*>(G) + (size_t)b * N_RX;
    #pragma unroll
    for (int r = 0; r < N_RX; r++) {
        float4 g = Gv[r];
        float basen = fmaf(g.x, rs0, g.y * rs1);
        SB += basen; SGZ += g.z; SGW += g.w;
        float t0 = fmaf(g.z, rm3, basen);
        float t1 = fmaf(g.z, rm1, basen);
        float t2 = fmaf(g.z, rp1, basen);
        float t3 = fmaf(g.z, rp3, basen);
        float cb = g.w * rp1;
        float A0 = ex2a(t0), A1 = ex2a(t1), A2 = ex2a(t2), A3 = ex2a(t3);
        float B  = ex2a(cb), iB = rcpa(B);
        float B3 = (B * B) * B, iB3 = (iB * iB) * iB;
        u64 Ap[4] = { pk2(A0, A0), pk2(A1, A1), pk2(A2, A2), pk2(A3, A3) };
        u64 Cc[2] = { pk2(iB3, iB), pk2(B, B3) };
        #pragma unroll
        for (int p = 0; p < 8; p++) {          // p = i2*2 + (i3>>1)
            u64 v2 = mul2(Ap[p >> 1], Cc[p & 1]);
            float vlo, vhi;
            upk2(vlo, vhi, v2);
            u64 e2 = pk2(fminf(vlo, 1.0f), fminf(vhi, 1.0f));
            u64 h2 = fma2(NH2, e2, ONE2);
            prod2[p] = mul2(prod2[p], mul2(e2, h2));
        }
    }
    const float Cp = rho2 * SGW;
    const float SY[4] = {S_M3, S_M1, S_P1, S_P3};
    const float RSY[4] = {rm3, rm1, rp1, rp3};
    float lp2[16];
    #pragma unroll
    for (int p = 0; p < 8; p++) {
        const int i2  = p >> 1;
        const int i3a = (p & 1) * 2;
        float Tp = -fmaf(SGZ, RSY[i2], SB);     // = -Sum_r t_{i2}
        float plo, phi;
        upk2(plo, phi, prod2[p]);
        lp2[i2 * 4 + i3a]     = fmaf(Cp, SY[i3a],     Tp) + lg2a(fmaxf(plo, 1e-37f));
        lp2[i2 * 4 + i3a + 1] = fmaf(Cp, SY[i3a + 1], Tp) + lg2a(fmaxf(phi, 1e-37f));
    }

    // ---- Load log_qi (log2 units), lazy per-row offsets ----
    float lq[4][4], off[4];
    const float4* Lv = reinterpret_cast<const float4*>(log_qi_in) + (size_t)b * 4;
    #pragma unroll
    for (int t = 0; t < 4; t++) {
        float4 v = Lv[t];
        lq[t][0] = v.x * LOG2E; lq[t][1] = v.y * LOG2E;
        lq[t][2] = v.z * LOG2E; lq[t][3] = v.w * LOG2E;
    }
    off[0] = 0.0f;               // row 0's first update uses the raw row
    off[1] = rowmax4(lq[1]);
    off[2] = rowmax4(lq[2]);
    off[3] = rowmax4(lq[3]);

    // ---- Initial unnormalized softmax pieces ----
    float f0, f1, S1, S2, S3, e2n[4], ul[4];
    {
        float e0 = ex2a(lq[0][0]), e1 = ex2a(lq[0][1]), e2 = ex2a(lq[0][2]), e3 = ex2a(lq[0][3]);
        f0 = qsel(e0, e1, e2, e3, i0);
    }
    {
        float e0 = ex2a(lq[1][0]-off[1]), e1 = ex2a(lq[1][1]-off[1]);
        float e2 = ex2a(lq[1][2]-off[1]), e3 = ex2a(lq[1][3]-off[1]);
        S1 = (e0 + e1) + (e2 + e3);
        f1 = qsel(e0, e1, e2, e3, i1);
    }
    {
        e2n[0] = ex2a(lq[2][0]-off[2]); e2n[1] = ex2a(lq[2][1]-off[2]);
        e2n[2] = ex2a(lq[2][2]-off[2]); e2n[3] = ex2a(lq[2][3]-off[2]);
        S2 = (e2n[0] + e2n[1]) + (e2n[2] + e2n[3]);
    }
    {
        float e0 = ex2a(lq[3][0]-off[3]), e1 = ex2a(lq[3][1]-off[3]);
        float e2 = ex2a(lq[3][2]-off[3]), e3 = ex2a(lq[3][3]-off[3]);
        S3 = (e0 + e1) + (e2 + e3);
        #pragma unroll
        for (int c = 0; c < 4; c++)
            ul[c] = fmaf(e3, lp2[c*4+3], fmaf(e2, lp2[c*4+2], fmaf(e1, lp2[c*4+1], e0 * lp2[c*4+0])));
    }
    float sum_wl = fmaf(e2n[3], ul[3], fmaf(e2n[2], ul[2], fmaf(e2n[1], ul[1], e2n[0] * ul[0])));
    float S23 = S2 * S3;
    const float oma = 1.0f - alpha;
    const unsigned FULL = 0xffffffffu;

    float S0n, S1n, f01, S01;

    // ---- xi = 0 : bucket i0 = hl>>2; reduce hl bits 0,1; scale 1/(S1*S2*S3) ----
    {
        float a = f1 * sum_wl;
        a += __shfl_xor_sync(FULL, a, 1);
        a += __shfl_xor_sync(FULL, a, 2);
        float a0 = __shfl_sync(FULL, a, base + 0);
        float a1 = __shfl_sync(FULL, a, base + 4);
        float a2 = __shfl_sync(FULL, a, base + 8);
        float a3 = __shfl_sync(FULL, a, base + 12);
        float sc = alpha * rcpa(S1 * S23);
        lq[0][0] = fmaf(oma, lq[0][0], sc * a0);
        lq[0][1] = fmaf(oma, lq[0][1], sc * a1);
        lq[0][2] = fmaf(oma, lq[0][2], sc * a2);
        lq[0][3] = fmaf(oma, lq[0][3], sc * a3);
        off[0] = rowmax4(lq[0]);
        float e0 = ex2a(lq[0][0]-off[0]), e1 = ex2a(lq[0][1]-off[0]);
        float e2 = ex2a(lq[0][2]-off[0]), e3 = ex2a(lq[0][3]-off[0]);
        S0n = (e0 + e1) + (e2 + e3);
        f0 = qsel(e0, e1, e2, e3, i0);
    }

    // ---- xi = 1 : bucket i1 = hl&3; reduce hl bits 2,3; scale 1/(S0n*S2*S3) ----
    {
        float a = f0 * sum_wl;
        a += __shfl_xor_sync(FULL, a, 4);
        a += __shfl_xor_sync(FULL, a, 8);
        float a0 = __shfl_sync(FULL, a, base + 0);
        float a1 = __shfl_sync(FULL, a, base + 1);
        float a2 = __shfl_sync(FULL, a, base + 2);
        float a3 = __shfl_sync(FULL, a, base + 3);
        float sc = alpha * rcpa(S0n * S23);
        float o = off[1];
        lq[1][0] = fmaf(oma, lq[1][0] - o, sc * a0);
        lq[1][1] = fmaf(oma, lq[1][1] - o, sc * a1);
        lq[1][2] = fmaf(oma, lq[1][2] - o, sc * a2);
        lq[1][3] = fmaf(oma, lq[1][3] - o, sc * a3);
        off[1] = rowmax4(lq[1]);
        float e0 = ex2a(lq[1][0]-off[1]), e1 = ex2a(lq[1][1]-off[1]);
        float e2 = ex2a(lq[1][2]-off[1]), e3 = ex2a(lq[1][3]-off[1]);
        S1n = (e0 + e1) + (e2 + e3);
        f01 = f0 * qsel(e0, e1, e2, e3, i1);
    }

    // ---- xi = 2 : bucket i2; fold 4 accs onto hl bits 0,1, reduce bits 2,3 ----
    float e2w[4], S2n;
    {
        float a0 = f01 * ul[0], a1 = f01 * ul[1], a2v = f01 * ul[2], a3v = f01 * ul[3];
        float kA = bit0 ? a1 : a0,   sA = bit0 ? a0 : a1;
        float kB = bit0 ? a3v : a2v, sB = bit0 ? a2v : a3v;
        float rA = kA + __shfl_xor_sync(FULL, sA, 1);   // bucket bit0
        float rB = kB + __shfl_xor_sync(FULL, sB, 1);   // bucket 2+bit0
        float k2 = bit1 ? rB : rA,   s2 = bit1 ? rA : rB;
        float a = k2 + __shfl_xor_sync(FULL, s2, 2);    // bucket hl&3
        a += __shfl_xor_sync(FULL, a, 4);
        a += __shfl_xor_sync(FULL, a, 8);
        float b0 = __shfl_sync(FULL, a, base + 0);
        float b1 = __shfl_sync(FULL, a, base + 1);
        float b2 = __shfl_sync(FULL, a, base + 2);
        float b3 = __shfl_sync(FULL, a, base + 3);
        S01 = S0n * S1n;
        float sc = alpha * rcpa(S01 * S3);
        float o = off[2];
        lq[2][0] = fmaf(oma, lq[2][0] - o, sc * b0);
        lq[2][1] = fmaf(oma, lq[2][1] - o, sc * b1);
        lq[2][2] = fmaf(oma, lq[2][2] - o, sc * b2);
        lq[2][3] = fmaf(oma, lq[2][3] - o, sc * b3);
        off[2] = rowmax4(lq[2]);
        e2w[0] = ex2a(lq[2][0]-off[2]); e2w[1] = ex2a(lq[2][1]-off[2]);
        e2w[2] = ex2a(lq[2][2]-off[2]); e2w[3] = ex2a(lq[2][3]-off[2]);
        S2n = (e2w[0] + e2w[1]) + (e2w[2] + e2w[3]);
    }

    // ---- xi = 3 : bucket i3; fold + reduce bits 2,3; scale 1/(S0n*S1n*S2n) ----
    {
        float v0 = 0.f, v1 = 0.f, v2 = 0.f, v3 = 0.f;
        #pragma unroll
        for (int c = 0; c < 4; c++) {
            v0 = fmaf(e2w[c], lp2[c*4+0], v0);
            v1 = fmaf(e2w[c], lp2[c*4+1], v1);
            v2 = fmaf(e2w[c], lp2[c*4+2], v2);
            v3 = fmaf(e2w[c], lp2[c*4+3], v3);
        }
        v0 *= f01; v1 *= f01; v2 *= f01; v3 *= f01;
        float kA = bit0 ? v1 : v0, sA = bit0 ? v0 : v1;
        float kB = bit0 ? v3 : v2, sB = bit0 ? v2 : v3;
        float rA = kA + __shfl_xor_sync(FULL, sA, 1);
        float rB = kB + __shfl_xor_sync(FULL, sB, 1);
        float k2 = bit1 ? rB : rA, s2 = bit1 ? rA : rB;
        float a = k2 + __shfl_xor_sync(FULL, s2, 2);    // bucket hl&3
        a += __shfl_xor_sync(FULL, a, 4);
        a += __shfl_xor_sync(FULL, a, 8);
        float b0 = __shfl_sync(FULL, a, base + 0);
        float b1 = __shfl_sync(FULL, a, base + 1);
        float b2 = __shfl_sync(FULL, a, base + 2);
        float b3 = __shfl_sync(FULL, a, base + 3);
        float sc = alpha * rcpa(S01 * S2n);
        float o = off[3];
        lq[3][0] = fmaf(oma, lq[3][0] - o, sc * b0);
        lq[3][1] = fmaf(oma, lq[3][1] - o, sc * b1);
        lq[3][2] = fmaf(oma, lq[3][2] - o, sc * b2);
        lq[3][3] = fmaf(oma, lq[3][3] - o, sc * b3);
        off[3] = rowmax4(lq[3]);
    }

    // ---- Output: (stored - off) * ln2; hl 0..3 of each half write rows 0..3 ----
    float o0 = off[0], o1 = off[1], o2 = off[2], o3 = off[3];
    float r0 = qsel(lq[0][0]-o0, lq[1][0]-o1, lq[2][0]-o2, lq[3][0]-o3, hl) * LN2;
    float r1 = qsel(lq[0][1]-o0, lq[1][1]-o1, lq[2][1]-o2, lq[3][1]-o3, hl) * LN2;
    float r2 = qsel(lq[0][2]-o0, lq[1][2]-o1, lq[2][2]-o2, lq[3][2]-o3, hl) * LN2;
    float r3 = qsel(lq[0][3]-o0, lq[1][3]-o1, lq[2][3]-o2, lq[3][3]-o3, hl) * LN2;
    if (hl < 4) {
        reinterpret_cast<float4*>(out)[(size_t)b * 4 + hl] = make_float4(r0, r1, r2, r3);
    }
}

extern "C" void kernel_launch(void* const* d_in, const int* in_sizes, int n_in,
                              void* d_out, int out_size)
{
    const float* log_qi    = (const float*)d_in[0]; // (N,4,4)
    const float* G         = (const float*)d_in[1]; // (N,8,4)
    const float* sqrt_2rho = (const float*)d_in[2]; // (N,)
    // d_in[3] = n_var, unused by reference
    const float* alpha     = (const float*)d_in[4]; // scalar

    float* out = (float*)d_out;

    // 2 items per warp -> NB/2 warps
    const int threads = 128;
    const int blocks  = (NB / 2) * 32 / threads;   // 4096
    mfnet_layer_kernel<<<blocks, threads>>>(log_qi, G, sqrt_2rho, alpha, out);
}

// round 9
// speedup vs baseline: 1.4321x; 1.0153x over previous
#include <cuda_runtime.h>

#define NB    32768
#define N_RX  8

// SYMS = {-3,-1,1,3}/sqrt(5)
#define S_M3 (-1.3416407864998738f)
#define S_M1 (-0.44721359549995793f)
#define S_P1 ( 0.44721359549995793f)
#define S_P3 ( 1.3416407864998738f)
#define LOG2E 1.4426950408889634f
#define LN2   0.6931471805599453f

typedef unsigned long long u64;

__device__ __forceinline__ float qsel(float a, float b, float c, float d, int i) {
    float ab = (i & 1) ? b : a;
    float cd = (i & 1) ? d : c;
    return (i & 2) ? cd : ab;
}
__device__ __forceinline__ float rowmax4(const float* v) {
    return fmaxf(fmaxf(v[0], v[1]), fmaxf(v[2], v[3]));
}
__device__ __forceinline__ float ex2a(float x) {
    float y; asm("ex2.approx.ftz.f32 %0, %1;" : "=f"(y) : "f"(x)); return y;
}
__device__ __forceinline__ float lg2a(float x) {
    float y; asm("lg2.approx.ftz.f32 %0, %1;" : "=f"(y) : "f"(x)); return y;
}
__device__ __forceinline__ float rcpa(float x) {
    float y; asm("rcp.approx.ftz.f32 %0, %1;" : "=f"(y) : "f"(x)); return y;
}
__device__ __forceinline__ u64 pk2(float lo, float hi) {
    u64 d; asm("mov.b64 %0, {%1, %2};" : "=l"(d) : "f"(lo), "f"(hi)); return d;
}
__device__ __forceinline__ void upk2(float& lo, float& hi, u64 d) {
    asm("mov.b64 {%0, %1}, %2;" : "=f"(lo), "=f"(hi) : "l"(d));
}
__device__ __forceinline__ u64 mul2(u64 a, u64 b) {
    u64 d; asm("mul.rn.f32x2 %0, %1, %2;" : "=l"(d) : "l"(a), "l"(b)); return d;
}
__device__ __forceinline__ u64 fma2(u64 a, u64 b, u64 c) {
    u64 d; asm("fma.rn.f32x2 %0, %1, %2, %3;" : "=l"(d) : "l"(a), "l"(b), "l"(c)); return d;
}

__global__ __launch_bounds__(128, 7)
void mfnet_layer_kernel(const float* __restrict__ log_qi_in,
                        const float* __restrict__ G,
                        const float* __restrict__ sqrt_2rho,
                        const float* __restrict__ alpha_ptr,
                        float* __restrict__ out)
{
    const int gtid = blockIdx.x * blockDim.x + threadIdx.x;
    const int w    = gtid >> 5;
    const int lane = gtid & 31;
    // Two items per warp: half-warps own item b = 2w + half.
    const int half = lane >> 4;
    const int hl   = lane & 15;
    const int b    = 2 * w + half;
    const int base = lane & 16;          // half-warp base lane for broadcasts

    const float alpha = __ldg(alpha_ptr);
    const float rho2  = __ldg(&sqrt_2rho[b]) * LOG2E;   // log2 units
    const float rho2n = -rho2;

    // k = i0*64 + i1*16 + i2*4 + i3 ; k = hl*16 + j
    // i0 = hl>>2 (bits 2,3), i1 = hl&3 (bits 0,1), i2 = j>>2, i3 = j&3
    const int i0 = hl >> 2;
    const int i1 = hl & 3;
    const int bit0 = hl & 1;
    const int bit1 = (hl >> 1) & 1;

    const float rm3 = rho2n * S_M3;
    const float rm1 = rho2n * S_M1;
    const float rp1 = rho2n * S_P1;
    const float rp3 = rho2n * S_P3;
    const float rs0 = qsel(rm3, rm1, rp1, rp3, i0);
    const float rs1 = qsel(rm3, rm1, rp1, rp3, i1);

    // ---- Laplace (log2 units), exp-factorized + f32x2-packed, 16 j per lane ----
    const u64 NH2  = pk2(-0.5f, -0.5f);
    const u64 ONE2 = pk2(1.0f, 1.0f);
    u64 prod2[8] = {ONE2, ONE2, ONE2, ONE2, ONE2, ONE2, ONE2, ONE2};
    float SB = 0.f, SGZ = 0.f, SGW = 0.f;
    const float4* Gv = reinterpret_cast<const float4*>(G) + (size_t)b * N_RX;
    #pragma unroll
    for (int r = 0; r < N_RX; r++) {
        float4 g = Gv[r];
        float basen = fmaf(g.x, rs0, g.y * rs1);
        SB += basen; SGZ += g.z; SGW += g.w;
        float t0 = fmaf(g.z, rm3, basen);
        float t1 = fmaf(g.z, rm1, basen);
        float t2 = fmaf(g.z, rp1, basen);
        float t3 = fmaf(g.z, rp3, basen);
        float cb = g.w * rp1;
        float A0 = ex2a(t0), A1 = ex2a(t1), A2 = ex2a(t2), A3 = ex2a(t3);
        float B  = ex2a(cb), iB = rcpa(B);
        float B3 = (B * B) * B, iB3 = (iB * iB) * iB;
        u64 Ap[4] = { pk2(A0, A0), pk2(A1, A1), pk2(A2, A2), pk2(A3, A3) };
        u64 Cc[2] = { pk2(iB3, iB), pk2(B, B3) };
        #pragma unroll
        for (int p = 0; p < 8; p++) {          // p = i2*2 + (i3>>1)
            u64 v2 = mul2(Ap[p >> 1], Cc[p & 1]);
            float vlo, vhi;
            upk2(vlo, vhi, v2);
            u64 e2 = pk2(fminf(vlo, 1.0f), fminf(vhi, 1.0f));
            u64 h2 = fma2(NH2, e2, ONE2);
            prod2[p] = mul2(prod2[p], mul2(e2, h2));
        }
    }
    const float Cp = rho2 * SGW;
    const float SY[4]  = {S_M3, S_M1, S_P1, S_P3};
    const float RSY[4] = {rm3, rm1, rp1, rp3};
    float T[4];
    #pragma unroll
    for (int c = 0; c < 4; c++) T[c] = -fmaf(SGZ, RSY[c], SB);
    float lp2[16];
    #pragma unroll
    for (int p = 0; p < 8; p++) {
        const int i2  = p >> 1;
        const int i3a = (p & 1) * 2;
        float plo, phi;
        upk2(plo, phi, prod2[p]);
        lp2[i2 * 4 + i3a]     = fmaf(Cp, SY[i3a],     T[i2]) + lg2a(fmaxf(plo, 1e-37f));
        lp2[i2 * 4 + i3a + 1] = fmaf(Cp, SY[i3a + 1], T[i2]) + lg2a(fmaxf(phi, 1e-37f));
    }

    const unsigned FULL = 0xffffffffu;
    const float oma = 1.0f - alpha;
    const float4* Lv = reinterpret_cast<const float4*>(log_qi_in) + (size_t)b * 4;

    // ---- Rows 0,1: distributed (each lane keeps only its own-index value) ----
    float4 v0 = Lv[0];
    float lq0own = qsel(v0.x, v0.y, v0.z, v0.w, i0) * LOG2E;
    float f0 = ex2a(lq0own);               // raw row, matches reference iter-0
    float4 v1 = Lv[1];
    float lq1own = qsel(v1.x, v1.y, v1.z, v1.w, i1) * LOG2E;
    float m1 = lq1own;                     // rowmax over i1 (bits 0,1)
    m1 = fmaxf(m1, __shfl_xor_sync(FULL, m1, 1));
    m1 = fmaxf(m1, __shfl_xor_sync(FULL, m1, 2));
    float f1 = ex2a(lq1own - m1);
    float S1 = f1 + __shfl_xor_sync(FULL, f1, 1);
    S1 += __shfl_xor_sync(FULL, S1, 2);

    // ---- Rows 2,3: full replication (all 4 exps needed per lane later) ----
    float lq[2][4], off2, off3;
    {
        float4 v = Lv[2];
        lq[0][0] = v.x * LOG2E; lq[0][1] = v.y * LOG2E;
        lq[0][2] = v.z * LOG2E; lq[0][3] = v.w * LOG2E;
        off2 = rowmax4(lq[0]);
    }
    {
        float4 v = Lv[3];
        lq[1][0] = v.x * LOG2E; lq[1][1] = v.y * LOG2E;
        lq[1][2] = v.z * LOG2E; lq[1][3] = v.w * LOG2E;
        off3 = rowmax4(lq[1]);
    }
    float e2n[4], S2, S3, ul[4];
    e2n[0] = ex2a(lq[0][0]-off2); e2n[1] = ex2a(lq[0][1]-off2);
    e2n[2] = ex2a(lq[0][2]-off2); e2n[3] = ex2a(lq[0][3]-off2);
    S2 = (e2n[0] + e2n[1]) + (e2n[2] + e2n[3]);
    {
        float e0 = ex2a(lq[1][0]-off3), e1 = ex2a(lq[1][1]-off3);
        float e2 = ex2a(lq[1][2]-off3), e3 = ex2a(lq[1][3]-off3);
        S3 = (e0 + e1) + (e2 + e3);
        #pragma unroll
        for (int c = 0; c < 4; c++)
            ul[c] = fmaf(e3, lp2[c*4+3], fmaf(e2, lp2[c*4+2], fmaf(e1, lp2[c*4+1], e0 * lp2[c*4+0])));
    }
    float sum_wl = fmaf(e2n[3], ul[3], fmaf(e2n[2], ul[2], fmaf(e2n[1], ul[1], e2n[0] * ul[0])));
    float S23 = S2 * S3;

    // ---- xi = 0 : bucket i0 (bits 2,3); reduce bits 0,1. Distributed update. ----
    float d0, S0n;
    {
        float a = f1 * sum_wl;
        a += __shfl_xor_sync(FULL, a, 1);
        a += __shfl_xor_sync(FULL, a, 2);          // own-bucket total in every lane
        float sc = alpha * rcpa(S1 * S23);
        float nv = fmaf(oma, lq0own, sc * a);
        float o = nv;
        o = fmaxf(o, __shfl_xor_sync(FULL, o, 4));
        o = fmaxf(o, __shfl_xor_sync(FULL, o, 8));
        d0 = nv - o;
        f0 = ex2a(d0);
        S0n = f0 + __shfl_xor_sync(FULL, f0, 4);
        S0n += __shfl_xor_sync(FULL, S0n, 8);
    }

    // ---- xi = 1 : bucket i1 (bits 0,1); reduce bits 2,3. Distributed update. ----
    float d1, S1n, f01;
    {
        float a = f0 * sum_wl;
        a += __shfl_xor_sync(FULL, a, 4);
        a += __shfl_xor_sync(FULL, a, 8);
        float sc = alpha * rcpa(S0n * S23);
        float nv = fmaf(oma, lq1own - m1, sc * a);
        float o = nv;
        o = fmaxf(o, __shfl_xor_sync(FULL, o, 1));
        o = fmaxf(o, __shfl_xor_sync(FULL, o, 2));
        d1 = nv - o;
        float e1n = ex2a(d1);
        S1n = e1n + __shfl_xor_sync(FULL, e1n, 1);
        S1n += __shfl_xor_sync(FULL, S1n, 2);
        f01 = f0 * e1n;
    }

    // ---- xi = 2 : bucket i2; fold onto hl bits 0,1, reduce bits 2,3. Full row. ----
    float e2w[4], S2n, S01;
    {
        float a0 = f01 * ul[0], a1 = f01 * ul[1], a2v = f01 * ul[2], a3v = f01 * ul[3];
        float kA = bit0 ? a1 : a0,   sA = bit0 ? a0 : a1;
        float kB = bit0 ? a3v : a2v, sB = bit0 ? a2v : a3v;
        float rA = kA + __shfl_xor_sync(FULL, sA, 1);
        float rB = kB + __shfl_xor_sync(FULL, sB, 1);
        float k2 = bit1 ? rB : rA,   s2 = bit1 ? rA : rB;
        float a = k2 + __shfl_xor_sync(FULL, s2, 2);    // bucket hl&3
        a += __shfl_xor_sync(FULL, a, 4);
        a += __shfl_xor_sync(FULL, a, 8);
        float b0 = __shfl_sync(FULL, a, base + 0);
        float b1 = __shfl_sync(FULL, a, base + 1);
        float b2 = __shfl_sync(FULL, a, base + 2);
        float b3 = __shfl_sync(FULL, a, base + 3);
        S01 = S0n * S1n;
        float sc = alpha * rcpa(S01 * S3);
        float o = off2;
        lq[0][0] = fmaf(oma, lq[0][0] - o, sc * b0);
        lq[0][1] = fmaf(oma, lq[0][1] - o, sc * b1);
        lq[0][2] = fmaf(oma, lq[0][2] - o, sc * b2);
        lq[0][3] = fmaf(oma, lq[0][3] - o, sc * b3);
        off2 = rowmax4(lq[0]);
        e2w[0] = ex2a(lq[0][0]-off2); e2w[1] = ex2a(lq[0][1]-off2);
        e2w[2] = ex2a(lq[0][2]-off2); e2w[3] = ex2a(lq[0][3]-off2);
        S2n = (e2w[0] + e2w[1]) + (e2w[2] + e2w[3]);
    }

    // ---- xi = 3 : bucket i3; fold + reduce bits 2,3. Full row. ----
    {
        float v0a = 0.f, v1a = 0.f, v2a = 0.f, v3a = 0.f;
        #pragma unroll
        for (int c = 0; c < 4; c++) {
            v0a = fmaf(e2w[c], lp2[c*4+0], v0a);
            v1a = fmaf(e2w[c], lp2[c*4+1], v1a);
            v2a = fmaf(e2w[c], lp2[c*4+2], v2a);
            v3a = fmaf(e2w[c], lp2[c*4+3], v3a);
        }
        v0a *= f01; v1a *= f01; v2a *= f01; v3a *= f01;
        float kA = bit0 ? v1a : v0a, sA = bit0 ? v0a : v1a;
        float kB = bit0 ? v3a : v2a, sB = bit0 ? v2a : v3a;
        float rA = kA + __shfl_xor_sync(FULL, sA, 1);
        float rB = kB + __shfl_xor_sync(FULL, sB, 1);
        float k2 = bit1 ? rB : rA, s2 = bit1 ? rA : rB;
        float a = k2 + __shfl_xor_sync(FULL, s2, 2);    // bucket hl&3
        a += __shfl_xor_sync(FULL, a, 4);
        a += __shfl_xor_sync(FULL, a, 8);
        float b0 = __shfl_sync(FULL, a, base + 0);
        float b1 = __shfl_sync(FULL, a, base + 1);
        float b2 = __shfl_sync(FULL, a, base + 2);
        float b3 = __shfl_sync(FULL, a, base + 3);
        float sc = alpha * rcpa(S01 * S2n);
        float o = off3;
        lq[1][0] = fmaf(oma, lq[1][0] - o, sc * b0);
        lq[1][1] = fmaf(oma, lq[1][1] - o, sc * b1);
        lq[1][2] = fmaf(oma, lq[1][2] - o, sc * b2);
        lq[1][3] = fmaf(oma, lq[1][3] - o, sc * b3);
        off3 = rowmax4(lq[1]);
    }

    // ---- Output: rows 0,1 gathered from distributed lanes; rows 2,3 from regs ----
    float x0 = __shfl_sync(FULL, d0, base + 0);
    float x1 = __shfl_sync(FULL, d0, base + 4);
    float x2 = __shfl_sync(FULL, d0, base + 8);
    float x3 = __shfl_sync(FULL, d0, base + 12);
    float y0 = __shfl_sync(FULL, d1, base + 0);
    float y1 = __shfl_sync(FULL, d1, base + 1);
    float y2 = __shfl_sync(FULL, d1, base + 2);
    float y3 = __shfl_sync(FULL, d1, base + 3);
    float r0 = qsel(x0, y0, lq[0][0]-off2, lq[1][0]-off3, hl) * LN2;
    float r1 = qsel(x1, y1, lq[0][1]-off2, lq[1][1]-off3, hl) * LN2;
    float r2 = qsel(x2, y2, lq[0][2]-off2, lq[1][2]-off3, hl) * LN2;
    float r3 = qsel(x3, y3, lq[0][3]-off2, lq[1][3]-off3, hl) * LN2;
    if (hl < 4) {
        reinterpret_cast<float4*>(out)[(size_t)b * 4 + hl] = make_float4(r0, r1, r2, r3);
    }
}

extern "C" void kernel_launch(void* const* d_in, const int* in_sizes, int n_in,
                              void* d_out, int out_size)
{
    const float* log_qi    = (const float*)d_in[0]; // (N,4,4)
    const float* G         = (const float*)d_in[1]; // (N,8,4)
    const float* sqrt_2rho = (const float*)d_in[2]; // (N,)
    // d_in[3] = n_var, unused by reference
    const float* alpha     = (const float*)d_in[4]; // scalar

    float* out = (float*)d_out;

    // 2 items per warp -> NB/2 warps
    const int threads = 128;
    const int blocks  = (NB / 2) * 32 / threads;   // 4096
    mfnet_layer_kernel<<<blocks, threads>>>(log_qi, G, sqrt_2rho, alpha, out);
}